// round 1
// baseline (speedup 1.0000x reference)
#include <cuda_runtime.h>
#include <math.h>

#define S_LEN 2048
#define BATCH 2
#define HID   2048
#define NH    16
#define HD    128
#define M_ROWS (S_LEN * BATCH)   // 4096
#define N3H    (3 * HID)         // 6144

// Scratch (allocation-free: __device__ globals)
__device__ float g_q[BATCH * NH * S_LEN * HD];
__device__ float g_k[BATCH * NH * S_LEN * HD];
__device__ float g_v[BATCH * NH * S_LEN * HD];
__device__ float g_ctx[M_ROWS * HID];

// ---------------------------------------------------------------------------
// QKV GEMM: mixed[4096,6144] = hidden[4096,2048] @ W[2048,6144] + bias
// Epilogue scatters into g_q/g_k/g_v with layout [b, h, s, d].
// 128x128 tile, BK=8, 256 threads, 8x8 per thread.
// ---------------------------------------------------------------------------
__global__ __launch_bounds__(256) void qkv_gemm_kernel(
    const float* __restrict__ A, const float* __restrict__ W,
    const float* __restrict__ bias)
{
    __shared__ float As[8][128];
    __shared__ float Bs[8][128];
    const int tid = threadIdx.x;
    const int tr = tid >> 4, tc = tid & 15;
    const int arow = tid >> 1, acol = (tid & 1) * 4;
    const int brow = tid >> 5, bcol = (tid & 31) * 4;
    const int rowBase = blockIdx.y * 128;
    const int colBase = blockIdx.x * 128;

    float acc[8][8];
#pragma unroll
    for (int i = 0; i < 8; i++)
#pragma unroll
        for (int j = 0; j < 8; j++) acc[i][j] = 0.0f;

    const float* Aptr = A + (size_t)(rowBase + arow) * HID + acol;
    const float* Wptr = W + (size_t)brow * N3H + colBase + bcol;

    for (int k0 = 0; k0 < HID; k0 += 8) {
        float4 av = *(const float4*)(Aptr + k0);
        float4 bv = *(const float4*)(Wptr + (size_t)k0 * N3H);
        As[acol + 0][arow] = av.x;
        As[acol + 1][arow] = av.y;
        As[acol + 2][arow] = av.z;
        As[acol + 3][arow] = av.w;
        *(float4*)&Bs[brow][bcol] = bv;
        __syncthreads();
#pragma unroll
        for (int k = 0; k < 8; ++k) {
            float ar[8], br[8];
            *(float4*)&ar[0] = *(const float4*)&As[k][tr * 8];
            *(float4*)&ar[4] = *(const float4*)&As[k][tr * 8 + 4];
            *(float4*)&br[0] = *(const float4*)&Bs[k][tc * 8];
            *(float4*)&br[4] = *(const float4*)&Bs[k][tc * 8 + 4];
#pragma unroll
            for (int i = 0; i < 8; i++)
#pragma unroll
                for (int j = 0; j < 8; j++)
                    acc[i][j] = fmaf(ar[i], br[j], acc[i][j]);
        }
        __syncthreads();
    }

    // Epilogue: add bias, scatter q/k/v -> [b,h,s,d]
#pragma unroll
    for (int i = 0; i < 8; i++) {
        const int r = rowBase + tr * 8 + i;
        const int s = r >> 1;       // BATCH == 2
        const int b = r & 1;
#pragma unroll
        for (int j = 0; j < 8; j++) {
            const int c = colBase + tc * 8 + j;
            const float v = acc[i][j] + bias[c];
            const int h = c / 384;
            const int jj = c - h * 384;
            const int which = jj >> 7;   // 0=q, 1=k, 2=v
            const int dd = jj & 127;
            float* dst = (which == 0) ? g_q : (which == 1 ? g_k : g_v);
            dst[(size_t)(((b * NH + h) * S_LEN) + s) * HD + dd] = v;
        }
    }
}

// ---------------------------------------------------------------------------
// Flash attention: one block = (b, h, 64-query tile). Online softmax.
// 64-key tiles; causal => only kt <= qt processed. Mask bytes honored.
// ---------------------------------------------------------------------------
#define BQ 64
#define BKT 64
#define QSTR 132          // padded row stride (floats)
#define PSTR 68
#define NQT (S_LEN / BQ)  // 32
#define ATTN_SMEM ((BQ * QSTR * 3 + BQ * PSTR) * 4)  // 118784 bytes

__global__ __launch_bounds__(256) void attn_kernel(
    const unsigned char* __restrict__ mask)
{
    extern __shared__ float sm[];
    float* sQ = sm;
    float* sK = sQ + BQ * QSTR;
    float* sV = sK + BKT * QSTR;
    float* sP = sV + BKT * QSTR;

    const int bid = blockIdx.x;
    const int qt = NQT - 1 - (bid % NQT);   // heavy tiles first
    const int bh = bid / NQT;               // b*NH + h
    const int b = bh / NH;
    const int h = bh % NH;
    const int q0 = qt * BQ;

    const int tid = threadIdx.x;
    const int ty = tid >> 4, tx = tid & 15;
    const float inv_norm = 0.08838834764831845f;  // 1/sqrt(128)

    // Load Q tile
    {
        const float* Qg = g_q + ((size_t)bh * S_LEN + q0) * HD;
#pragma unroll
        for (int it = 0; it < 8; ++it) {
            int e = tid + it * 256;           // float4 index, 2048 total
            int row = e >> 5;
            int c4 = (e & 31) * 4;
            *(float4*)&sQ[row * QSTR + c4] = *(const float4*)&Qg[row * HD + c4];
        }
    }

    float m_i[4], l_i[4], o[4][8];
#pragma unroll
    for (int ii = 0; ii < 4; ii++) {
        m_i[ii] = -1e30f; l_i[ii] = 0.0f;
#pragma unroll
        for (int cc = 0; cc < 8; cc++) o[ii][cc] = 0.0f;
    }

    for (int kt = 0; kt <= qt; ++kt) {
        const int k0 = kt * BKT;
        __syncthreads();  // prior PV readers done before overwrite
        {
            const float* Kg = g_k + ((size_t)bh * S_LEN + k0) * HD;
            const float* Vg = g_v + ((size_t)bh * S_LEN + k0) * HD;
#pragma unroll
            for (int it = 0; it < 8; ++it) {
                int e = tid + it * 256;
                int row = e >> 5;
                int c4 = (e & 31) * 4;
                *(float4*)&sK[row * QSTR + c4] = *(const float4*)&Kg[row * HD + c4];
                *(float4*)&sV[row * QSTR + c4] = *(const float4*)&Vg[row * HD + c4];
            }
        }
        __syncthreads();

        // S = Q K^T  (64x64, 4x4 per thread)
        float acc[4][4];
#pragma unroll
        for (int ii = 0; ii < 4; ii++)
#pragma unroll
            for (int jj = 0; jj < 4; jj++) acc[ii][jj] = 0.0f;

        const float4* q4 = (const float4*)sQ;
        const float4* k4 = (const float4*)sK;
#pragma unroll 8
        for (int d4 = 0; d4 < 32; ++d4) {
            float4 qv[4], kv[4];
#pragma unroll
            for (int ii = 0; ii < 4; ii++) qv[ii] = q4[(ty * 4 + ii) * 33 + d4];
#pragma unroll
            for (int jj = 0; jj < 4; jj++) kv[jj] = k4[(tx * 4 + jj) * 33 + d4];
#pragma unroll
            for (int ii = 0; ii < 4; ii++)
#pragma unroll
                for (int jj = 0; jj < 4; jj++) {
                    acc[ii][jj] = fmaf(qv[ii].x, kv[jj].x, acc[ii][jj]);
                    acc[ii][jj] = fmaf(qv[ii].y, kv[jj].y, acc[ii][jj]);
                    acc[ii][jj] = fmaf(qv[ii].z, kv[jj].z, acc[ii][jj]);
                    acc[ii][jj] = fmaf(qv[ii].w, kv[jj].w, acc[ii][jj]);
                }
        }

        // scale + mask + online softmax update, write P to smem
#pragma unroll
        for (int ii = 0; ii < 4; ii++) {
            const int sg = q0 + ty * 4 + ii;
            const unsigned char* mrow = mask + ((size_t)b * S_LEN + sg) * S_LEN + k0;
            float vmax = -1e30f;
#pragma unroll
            for (int jj = 0; jj < 4; jj++) {
                const int tl = tx * 4 + jj;
                const int tg = k0 + tl;
                const bool masked = (tg > sg) || (mrow[tl] != 0);
                const float sval = masked ? -10000.0f : acc[ii][jj] * inv_norm;
                acc[ii][jj] = sval;
                vmax = fmaxf(vmax, sval);
            }
#pragma unroll
            for (int off = 8; off >= 1; off >>= 1)
                vmax = fmaxf(vmax, __shfl_xor_sync(0xffffffffu, vmax, off, 16));
            const float m_new = fmaxf(m_i[ii], vmax);
            const float corr = __expf(m_i[ii] - m_new);
            float lsum = 0.0f;
#pragma unroll
            for (int jj = 0; jj < 4; jj++) {
                const float p = __expf(acc[ii][jj] - m_new);
                lsum += p;
                sP[(ty * 4 + ii) * PSTR + tx * 4 + jj] = p;
            }
#pragma unroll
            for (int off = 8; off >= 1; off >>= 1)
                lsum += __shfl_xor_sync(0xffffffffu, lsum, off, 16);
            l_i[ii] = l_i[ii] * corr + lsum;
            m_i[ii] = m_new;
#pragma unroll
            for (int cc = 0; cc < 8; cc++) o[ii][cc] *= corr;
        }
        __syncthreads();

        // O += P @ V  (each thread: 4 rows x 8 cols at col base tx*8)
        const float4* v4 = (const float4*)sV;
#pragma unroll 4
        for (int j = 0; j < BKT; ++j) {
            const float4 va = v4[j * 33 + tx * 2];
            const float4 vb = v4[j * 33 + tx * 2 + 1];
#pragma unroll
            for (int ii = 0; ii < 4; ii++) {
                const float p = sP[(ty * 4 + ii) * PSTR + j];
                o[ii][0] = fmaf(p, va.x, o[ii][0]);
                o[ii][1] = fmaf(p, va.y, o[ii][1]);
                o[ii][2] = fmaf(p, va.z, o[ii][2]);
                o[ii][3] = fmaf(p, va.w, o[ii][3]);
                o[ii][4] = fmaf(p, vb.x, o[ii][4]);
                o[ii][5] = fmaf(p, vb.y, o[ii][5]);
                o[ii][6] = fmaf(p, vb.z, o[ii][6]);
                o[ii][7] = fmaf(p, vb.w, o[ii][7]);
            }
        }
    }

    // normalize + write context [s, b, H]
#pragma unroll
    for (int ii = 0; ii < 4; ii++) {
        const int sg = q0 + ty * 4 + ii;
        const float inv_l = 1.0f / l_i[ii];
        float* dst = g_ctx + ((size_t)sg * BATCH + b) * HID + h * HD + tx * 8;
        float4 r0, r1;
        r0.x = o[ii][0] * inv_l; r0.y = o[ii][1] * inv_l;
        r0.z = o[ii][2] * inv_l; r0.w = o[ii][3] * inv_l;
        r1.x = o[ii][4] * inv_l; r1.y = o[ii][5] * inv_l;
        r1.z = o[ii][6] * inv_l; r1.w = o[ii][7] * inv_l;
        *(float4*)dst = r0;
        *(float4*)(dst + 4) = r1;
    }
}

// ---------------------------------------------------------------------------
// Proj GEMM: out[4096,2048] = g_ctx[4096,2048] @ Wp[2048,2048]  (no bias add)
// ---------------------------------------------------------------------------
__global__ __launch_bounds__(256) void proj_gemm_kernel(
    const float* __restrict__ W, float* __restrict__ out)
{
    __shared__ float As[8][128];
    __shared__ float Bs[8][128];
    const int tid = threadIdx.x;
    const int tr = tid >> 4, tc = tid & 15;
    const int arow = tid >> 1, acol = (tid & 1) * 4;
    const int brow = tid >> 5, bcol = (tid & 31) * 4;
    const int rowBase = blockIdx.y * 128;
    const int colBase = blockIdx.x * 128;

    float acc[8][8];
#pragma unroll
    for (int i = 0; i < 8; i++)
#pragma unroll
        for (int j = 0; j < 8; j++) acc[i][j] = 0.0f;

    const float* Aptr = g_ctx + (size_t)(rowBase + arow) * HID + acol;
    const float* Wptr = W + (size_t)brow * HID + colBase + bcol;

    for (int k0 = 0; k0 < HID; k0 += 8) {
        float4 av = *(const float4*)(Aptr + k0);
        float4 bv = *(const float4*)(Wptr + (size_t)k0 * HID);
        As[acol + 0][arow] = av.x;
        As[acol + 1][arow] = av.y;
        As[acol + 2][arow] = av.z;
        As[acol + 3][arow] = av.w;
        *(float4*)&Bs[brow][bcol] = bv;
        __syncthreads();
#pragma unroll
        for (int k = 0; k < 8; ++k) {
            float ar[8], br[8];
            *(float4*)&ar[0] = *(const float4*)&As[k][tr * 8];
            *(float4*)&ar[4] = *(const float4*)&As[k][tr * 8 + 4];
            *(float4*)&br[0] = *(const float4*)&Bs[k][tc * 8];
            *(float4*)&br[4] = *(const float4*)&Bs[k][tc * 8 + 4];
#pragma unroll
            for (int i = 0; i < 8; i++)
#pragma unroll
                for (int j = 0; j < 8; j++)
                    acc[i][j] = fmaf(ar[i], br[j], acc[i][j]);
        }
        __syncthreads();
    }

#pragma unroll
    for (int i = 0; i < 8; i++) {
        float* dst = out + (size_t)(rowBase + tr * 8 + i) * HID + colBase + tc * 8;
        float4 r0, r1;
        r0.x = acc[i][0]; r0.y = acc[i][1]; r0.z = acc[i][2]; r0.w = acc[i][3];
        r1.x = acc[i][4]; r1.y = acc[i][5]; r1.z = acc[i][6]; r1.w = acc[i][7];
        *(float4*)dst = r0;
        *(float4*)(dst + 4) = r1;
    }
}

__global__ void copy_bias_kernel(const float* __restrict__ bias, float* __restrict__ dst)
{
    int i = blockIdx.x * blockDim.x + threadIdx.x;
    if (i < HID) dst[i] = bias[i];
}

// ---------------------------------------------------------------------------
extern "C" void kernel_launch(void* const* d_in, const int* in_sizes, int n_in,
                              void* d_out, int out_size)
{
    const float* hidden   = (const float*)d_in[0];
    const unsigned char* mask = (const unsigned char*)d_in[1];
    const float* qkv_w    = (const float*)d_in[2];
    const float* qkv_b    = (const float*)d_in[3];
    const float* proj_w   = (const float*)d_in[4];
    const float* proj_b   = (const float*)d_in[5];
    float* out = (float*)d_out;

    // Opt-in to >48KB dynamic smem (idempotent; no allocation, capture-safe)
    cudaFuncSetAttribute(attn_kernel,
                         cudaFuncAttributeMaxDynamicSharedMemorySize, ATTN_SMEM);

    dim3 qkvGrid(N3H / 128, M_ROWS / 128);   // 48 x 32
    qkv_gemm_kernel<<<qkvGrid, 256>>>(hidden, qkv_w, qkv_b);

    attn_kernel<<<BATCH * NH * NQT, 256, ATTN_SMEM>>>(mask);

    dim3 projGrid(HID / 128, M_ROWS / 128);  // 16 x 32
    proj_gemm_kernel<<<projGrid, 256>>>(proj_w, out);

    if (out_size > M_ROWS * HID) {
        copy_bias_kernel<<<(HID + 255) / 256, 256>>>(proj_b, out + (size_t)M_ROWS * HID);
    }
}